// round 9
// baseline (speedup 1.0000x reference)
#include <cuda_runtime.h>

typedef unsigned long long ull;

#define B 8192
#define L 10
#define D 128
#define H 64
#define G4 256          // 4*H
#define OUT 5
#define TILE 64
#define NTHR 256
#define ASTR 64
#define QSTR 68
#define CSTR 68

// ------------------- global scratch -------------------
__device__ float g_at[(size_t)B * D];           // encoder attention weights (t-invariant)
__device__ float g_gatex[(size_t)B * L * G4];   // (at*x_t)@Wih^T + bias, packed acc layout
__device__ float g_xenc[(size_t)B * L * H];     // encoder hidden sequence
__device__ float g_pre[(size_t)B * L * H];      // x_enc @ W1x^T
__device__ float g_Wenc[192 * G4];              // [k][j*4+g]  k: 0..127 Wih, 128..191 Whh
__device__ float g_Wdec[69 * G4];               // [k][j*4+g]  k: 0..4 Wih, 5..68 Whh
__device__ float g_Wq[128 * H];                 // [k][hh]     k: 0..63 W1h, 64..127 W1c

// ------------------- helpers -------------------
__device__ __forceinline__ ull pack2(float x, float y) {
    ull r; asm("mov.b64 %0, {%1, %2};" : "=l"(r) : "f"(x), "f"(y)); return r;
}
__device__ __forceinline__ ull dup2(float x) { return pack2(x, x); }
__device__ __forceinline__ float2 unpack2(ull v) {
    float2 f; asm("mov.b64 {%0, %1}, %2;" : "=f"(f.x), "=f"(f.y) : "l"(v)); return f;
}
__device__ __forceinline__ ull fma2(ull a, ull b, ull c) {
    ull d; asm("fma.rn.f32x2 %0, %1, %2, %3;" : "=l"(d) : "l"(a), "l"(b), "l"(c)); return d;
}
__device__ __forceinline__ float sigf(float x) {
    return __fdividef(1.f, 1.f + __expf(-x));
}
__device__ __forceinline__ float tanh_acc(float x) {
    return 1.f - __fdividef(2.f, __expf(2.f * x) + 1.f);
}
__device__ __forceinline__ float tanh_ap(float x) {
    float y; asm("tanh.approx.f32 %0, %1;" : "=f"(y) : "f"(x)); return y;
}

// =============================================================
// K0: repack weights
// =============================================================
__global__ void k_repack(const float* __restrict__ eWih, const float* __restrict__ eWhh,
                         const float* __restrict__ dWih, const float* __restrict__ dWhh,
                         const float* __restrict__ w1) {
    int idx = blockIdx.x * 256 + threadIdx.x;
    if (idx < 192 * G4) {
        int k = idx >> 8, c4 = idx & 255, j = c4 >> 2, g = c4 & 3;
        g_Wenc[idx] = (k < 128) ? eWih[(g * H + j) * D + k]
                                : eWhh[(g * H + j) * H + (k - 128)];
        return;
    }
    idx -= 192 * G4;
    if (idx < 69 * G4) {
        int k = idx >> 8, c4 = idx & 255, j = c4 >> 2, g = c4 & 3;
        g_Wdec[idx] = (k < 5) ? dWih[(g * H + j) * OUT + k]
                              : dWhh[(g * H + j) * H + (k - 5)];
        return;
    }
    idx -= 69 * G4;
    if (idx < 128 * H) {
        int k = idx >> 6, hh = idx & 63;
        g_Wq[idx] = (k < 64) ? w1[hh * 192 + k] : w1[hh * 192 + 64 + (k - 64)];
    }
}

// =============================================================
// K1: encoder attention weights: at[b,:] = softmax_d(x[b,:,:]^T @ wx)
// (h/c score terms + bias are per-row constants -> exact)
// =============================================================
__global__ __launch_bounds__(NTHR) void k_atten(const float* __restrict__ x,
                                                const float* __restrict__ enc_attn_w) {
    const int tid = threadIdx.x;
    const int rowp = tid >> 2, dg = tid & 3;
    const int b = blockIdx.x * 64 + rowp;

    float wx[L];
#pragma unroll
    for (int l = 0; l < L; l++) wx[l] = __ldg(enc_attn_w + 2 * H + l);
    float4 at4[8];
#pragma unroll
    for (int i = 0; i < 8; i++) at4[i] = make_float4(0.f, 0.f, 0.f, 0.f);
    const float* xp = x + (size_t)b * L * D + dg * 32;
#pragma unroll
    for (int l = 0; l < L; l++) {
#pragma unroll
        for (int i = 0; i < 8; i++) {
            float4 v = *(const float4*)(xp + l * D + i * 4);
            at4[i].x = fmaf(v.x, wx[l], at4[i].x);
            at4[i].y = fmaf(v.y, wx[l], at4[i].y);
            at4[i].z = fmaf(v.z, wx[l], at4[i].z);
            at4[i].w = fmaf(v.w, wx[l], at4[i].w);
        }
    }
    float m = -1e30f;
#pragma unroll
    for (int i = 0; i < 8; i++)
        m = fmaxf(m, fmaxf(fmaxf(at4[i].x, at4[i].y), fmaxf(at4[i].z, at4[i].w)));
    m = fmaxf(m, __shfl_xor_sync(0xFFFFFFFFu, m, 1));
    m = fmaxf(m, __shfl_xor_sync(0xFFFFFFFFu, m, 2));
    float s = 0.f;
#pragma unroll
    for (int i = 0; i < 8; i++) {
        at4[i].x = __expf(at4[i].x - m); at4[i].y = __expf(at4[i].y - m);
        at4[i].z = __expf(at4[i].z - m); at4[i].w = __expf(at4[i].w - m);
        s += at4[i].x + at4[i].y + at4[i].z + at4[i].w;
    }
    s += __shfl_xor_sync(0xFFFFFFFFu, s, 1);
    s += __shfl_xor_sync(0xFFFFFFFFu, s, 2);
    float inv = __fdividef(1.f, s);
#pragma unroll
    for (int i = 0; i < 8; i++) {
        at4[i].x *= inv; at4[i].y *= inv; at4[i].z *= inv; at4[i].w *= inv;
        *(float4*)(g_at + (size_t)b * D + dg * 32 + i * 4) = at4[i];
    }
}

// =============================================================
// K2: hoisted x-projection: g_gatex[r][c] = (at_b ⊙ x_r) @ Wih^T + bias
// r = b*L + t (81920 rows). Non-recurrent -> 2 CTAs/SM, near FFMA roof.
// Output layout = packed acc pairs (col c4 = j*4+g), 64-bit words.
// =============================================================
__global__ __launch_bounds__(NTHR, 2) void k_gatex(
    const float* __restrict__ x,
    const float* __restrict__ bih, const float* __restrict__ bhh) {
    extern __shared__ float sgx[];
    float* As = sgx;                 // [128][64]
    float* Bs = As + 128 * ASTR;     // [16][256]

    const int tid = threadIdx.x;
    const int rt = tid & 7, jc = tid >> 3;
    const int r0 = rt * 8, j0 = jc * 2;
    const int R0 = blockIdx.x * 64;
    const int rowp = tid >> 2, dg = tid & 3;

    // stage As[k][row] = at[b][k] * x[r][k]
    {
        int r = R0 + rowp;
        int b = r / L;
        const float* xp = x + (size_t)r * D + dg * 32;
        const float* ap = g_at + (size_t)b * D + dg * 32;
#pragma unroll
        for (int i = 0; i < 8; i++) {
            float4 xv = *(const float4*)(xp + i * 4);
            float4 av = *(const float4*)(ap + i * 4);
            int k = dg * 32 + i * 4;
            As[(k + 0) * ASTR + rowp] = xv.x * av.x;
            As[(k + 1) * ASTR + rowp] = xv.y * av.y;
            As[(k + 2) * ASTR + rowp] = xv.z * av.z;
            As[(k + 3) * ASTR + rowp] = xv.w * av.w;
        }
    }
    // acc init = fused bias
    ull acc[8][4];
    {
        float bres[8];
#pragma unroll
        for (int g = 0; g < 4; g++) {
            bres[g]     = bih[g * H + j0]     + bhh[g * H + j0];
            bres[4 + g] = bih[g * H + j0 + 1] + bhh[g * H + j0 + 1];
        }
        ull bp0 = pack2(bres[0], bres[1]), bp1 = pack2(bres[2], bres[3]);
        ull bp2 = pack2(bres[4], bres[5]), bp3 = pack2(bres[6], bres[7]);
#pragma unroll
        for (int i = 0; i < 8; i++) {
            acc[i][0] = bp0; acc[i][1] = bp1; acc[i][2] = bp2; acc[i][3] = bp3;
        }
    }
    __syncthreads();

    for (int kb = 0; kb < 8; kb++) {
        const float4* wp = (const float4*)(g_Wenc + kb * 16 * G4) + tid * 4;
        float4 w0 = wp[0], w1 = wp[1], w2 = wp[2], w3 = wp[3];
        if (kb) __syncthreads();       // prior chunk reads done
        float4* b4 = (float4*)Bs + tid * 4;
        b4[0] = w0; b4[1] = w1; b4[2] = w2; b4[3] = w3;
        __syncthreads();
#pragma unroll
        for (int kk = 0; kk < 16; kk++) {
            const float* ap = As + (kb * 16 + kk) * ASTR;
            float4 a0 = *(const float4*)(ap + r0);
            float4 a1 = *(const float4*)(ap + r0 + 4);
            const ulonglong2* vp = (const ulonglong2*)(Bs + kk * G4 + jc * 8);
            ulonglong2 vA = vp[0], vB = vp[1];
            float av[8] = {a0.x, a0.y, a0.z, a0.w, a1.x, a1.y, a1.z, a1.w};
#pragma unroll
            for (int i = 0; i < 8; i++) {
                ull ad = dup2(av[i]);
                acc[i][0] = fma2(ad, vA.x, acc[i][0]);
                acc[i][1] = fma2(ad, vA.y, acc[i][1]);
                acc[i][2] = fma2(ad, vB.x, acc[i][2]);
                acc[i][3] = fma2(ad, vB.y, acc[i][3]);
            }
        }
    }
    // store packed acc pairs
#pragma unroll
    for (int i = 0; i < 8; i++) {
        float* pb = g_gatex + (size_t)(R0 + r0 + i) * G4 + jc * 8;
        *(ulonglong2*)(pb)     = make_ulonglong2(acc[i][0], acc[i][1]);
        *(ulonglong2*)(pb + 4) = make_ulonglong2(acc[i][2], acc[i][3]);
    }
}

// =============================================================
// K3: fused recurrent network. One CTA owns 64 batch rows:
// encoder recurrence (h@Whh only, Whh smem-resident), then decoder.
// =============================================================
__global__ __launch_bounds__(NTHR, 1) void k_net(
    const float* __restrict__ h0, const float* __restrict__ c0,
    const float* __restrict__ w1,
    const float* __restrict__ y_hist, const float* __restrict__ h0d,
    const float* __restrict__ c0d,
    const float* __restrict__ dec_attn_b1, const float* __restrict__ dec_attn_w2,
    const float* __restrict__ dec_bih, const float* __restrict__ dec_bhh,
    const float* __restrict__ fc_w, const float* __restrict__ fc_b,
    const float* __restrict__ fcout_w, const float* __restrict__ fcout_b,
    float* __restrict__ out) {
    extern __shared__ float sm[];

    const int tid = threadIdx.x;
    const int rt = tid & 7, jc = tid >> 3;
    const int r0 = rt * 8, j0 = jc * 2;
    const int b0 = blockIdx.x * TILE;

    // =========================================================
    // ENCODER PHASE — smem: Whh_s[64][256], As_h[64][64], Ws1x[64][64]
    // =========================================================
    {
        float* Whh_s = sm;                   // 64 KB, resident all steps
        float* As_h  = Whh_s + 64 * G4;      // h transposed [j][row]
        float* Ws1x  = As_h + 64 * ASTR;     // [e][hh]

        // stage Whh (once)
        {
            const float4* src = (const float4*)(g_Wenc + 128 * G4);
            float4* dst = (float4*)Whh_s;
            for (int i = tid; i < 64 * G4 / 4; i += NTHR) dst[i] = src[i];
        }
        // stage Ws1x[e][hh] = W1x[hh][e]
        for (int i = tid; i < 64 * 64; i += NTHR) {
            int e = i >> 6, hh = i & 63;
            Ws1x[e * 64 + hh] = w1[hh * 192 + 128 + e];
        }
        // stage h0 transposed
        {
            int row = tid >> 2, jg = tid & 3;
            const float* hp = h0 + (size_t)(b0 + row) * H + jg * 16;
#pragma unroll
            for (int i = 0; i < 4; i++) {
                float4 v = *(const float4*)(hp + i * 4);
                int j = jg * 16 + i * 4;
                As_h[(j + 0) * ASTR + row] = v.x;
                As_h[(j + 1) * ASTR + row] = v.y;
                As_h[(j + 2) * ASTR + row] = v.z;
                As_h[(j + 3) * ASTR + row] = v.w;
            }
        }
        float cr0[8], cr1[8];
#pragma unroll
        for (int i = 0; i < 8; i++) {
            cr0[i] = c0[(size_t)(b0 + r0 + i) * H + j0];
            cr1[i] = c0[(size_t)(b0 + r0 + i) * H + j0 + 1];
        }
        __syncthreads();

        for (int t = 0; t < L; t++) {
            // ---- acc init from hoisted gatex (bias included) ----
            ull acc[8][4];
#pragma unroll
            for (int i = 0; i < 8; i++) {
                const float* pb = g_gatex + ((size_t)(b0 + r0 + i) * L + t) * G4 + jc * 8;
                ulonglong2 v0 = *(const ulonglong2*)(pb);
                ulonglong2 v1 = *(const ulonglong2*)(pb + 4);
                acc[i][0] = v0.x; acc[i][1] = v0.y;
                acc[i][2] = v1.x; acc[i][3] = v1.y;
            }
            // ---- recurrent GEMM: += h @ Whh^T (Whh resident, no syncs) ----
#pragma unroll 8
            for (int kk = 0; kk < 64; kk++) {
                const float* ap = As_h + kk * ASTR;
                float4 a0 = *(const float4*)(ap + r0);
                float4 a1 = *(const float4*)(ap + r0 + 4);
                const ulonglong2* vp = (const ulonglong2*)(Whh_s + kk * G4 + jc * 8);
                ulonglong2 vA = vp[0], vB = vp[1];
                float av[8] = {a0.x, a0.y, a0.z, a0.w, a1.x, a1.y, a1.z, a1.w};
#pragma unroll
                for (int i = 0; i < 8; i++) {
                    ull ad = dup2(av[i]);
                    acc[i][0] = fma2(ad, vA.x, acc[i][0]);
                    acc[i][1] = fma2(ad, vA.y, acc[i][1]);
                    acc[i][2] = fma2(ad, vB.x, acc[i][2]);
                    acc[i][3] = fma2(ad, vB.y, acc[i][3]);
                }
            }
            __syncthreads();   // h reads done before overwrite

            // ---- activations ----
#pragma unroll
            for (int i = 0; i < 8; i++) {
                float2 u0 = unpack2(acc[i][0]), u1 = unpack2(acc[i][1]);
                float2 u2 = unpack2(acc[i][2]), u3 = unpack2(acc[i][3]);
                float cn0 = sigf(u0.y) * cr0[i] + sigf(u0.x) * tanh_acc(u1.x);
                float hn0 = sigf(u1.y) * tanh_acc(cn0);
                float cn1 = sigf(u2.y) * cr1[i] + sigf(u2.x) * tanh_acc(u3.x);
                float hn1 = sigf(u3.y) * tanh_acc(cn1);
                cr0[i] = cn0; cr1[i] = cn1;
                As_h[(j0) * ASTR + r0 + i]     = hn0;
                As_h[(j0 + 1) * ASTR + r0 + i] = hn1;
                *(float2*)(g_xenc + ((size_t)(b0 + r0 + i) * L + t) * H + j0) =
                    make_float2(hn0, hn1);
            }
            __syncthreads();   // h visible

            // ---- fused pre-GEMM: pre = h @ W1x^T ----
            {
                ull p0c0 = 0, p1c0 = 0, p2c0 = 0, p3c0 = 0;
                ull p0c1 = 0, p1c1 = 0, p2c1 = 0, p3c1 = 0;
#pragma unroll 8
                for (int e = 0; e < 64; e++) {
                    const float* hp = As_h + e * ASTR;
                    ulonglong2 hA = *(const ulonglong2*)(hp + r0);
                    ulonglong2 hB = *(const ulonglong2*)(hp + r0 + 4);
                    float2 w = *(const float2*)(Ws1x + e * 64 + j0);
                    ull w0 = dup2(w.x), w1d = dup2(w.y);
                    p0c0 = fma2(hA.x, w0, p0c0); p1c0 = fma2(hA.y, w0, p1c0);
                    p2c0 = fma2(hB.x, w0, p2c0); p3c0 = fma2(hB.y, w0, p3c0);
                    p0c1 = fma2(hA.x, w1d, p0c1); p1c1 = fma2(hA.y, w1d, p1c1);
                    p2c1 = fma2(hB.x, w1d, p2c1); p3c1 = fma2(hB.y, w1d, p3c1);
                }
                float2 a0 = unpack2(p0c0), b0v = unpack2(p0c1);
                float2 a1 = unpack2(p1c0), b1v = unpack2(p1c1);
                float2 a2 = unpack2(p2c0), b2v = unpack2(p2c1);
                float2 a3 = unpack2(p3c0), b3v = unpack2(p3c1);
                float* pb = g_pre + ((size_t)(b0 + r0) * L + t) * H + j0;
                const size_t rs = (size_t)L * H;
                *(float2*)(pb + 0 * rs) = make_float2(a0.x, b0v.x);
                *(float2*)(pb + 1 * rs) = make_float2(a0.y, b0v.y);
                *(float2*)(pb + 2 * rs) = make_float2(a1.x, b1v.x);
                *(float2*)(pb + 3 * rs) = make_float2(a1.y, b1v.y);
                *(float2*)(pb + 4 * rs) = make_float2(a2.x, b2v.x);
                *(float2*)(pb + 5 * rs) = make_float2(a2.y, b2v.y);
                *(float2*)(pb + 6 * rs) = make_float2(a3.x, b3v.x);
                *(float2*)(pb + 7 * rs) = make_float2(a3.y, b3v.y);
            }
            // pre reads + next GEMM reads both precede next activation's sync
        }
    }
    __syncthreads();   // encoder smem dead; repartition for decoder

    // =========================================================
    // DECODER PHASE (unchanged from best-measured version)
    // =========================================================
    {
        float* Wdec  = sm;
        float* Wq    = Wdec + 69 * G4;
        float* Acs   = Wq + 128 * H;
        float* As2   = Acs + 128 * 64;
        float* q_s   = As2 + 5 * 64;
        float* ctx_s = q_s + 64 * QSTR;
        float* w2_s  = ctx_s + 64 * CSTR;
        float* b1_s  = w2_s + 64;
        float* fcw_s = b1_s + 64;
        float* fcb_s = fcw_s + 5 * 72;
        float* fow_s = fcb_s + 8;
        float* fob_s = fow_s + 5 * 128;

        const int rowq = tid >> 2, q4 = tid & 3;

        for (int i = tid; i < 69 * G4; i += NTHR)  Wdec[i] = g_Wdec[i];
        for (int i = tid; i < 128 * H; i += NTHR)  Wq[i]   = g_Wq[i];
        if (tid < 64) { w2_s[tid] = dec_attn_w2[tid]; b1_s[tid] = dec_attn_b1[tid]; }
        for (int i = tid; i < 5 * 69; i += NTHR) {
            int o = i / 69, k = i % 69;
            fcw_s[o * 72 + k] = fc_w[i];
        }
        for (int i = tid; i < 5 * 128; i += NTHR) fow_s[i] = fcout_w[i];
        if (tid < 5) { fcb_s[tid] = fc_b[tid]; fob_s[tid] = fcout_b[tid]; }

        {   // h0/c0 transposed
            int row = tid >> 2, jg = tid & 3;
#pragma unroll
            for (int i = 0; i < 4; i++) {
                int j = jg * 16 + i * 4;
                float4 hv = *(const float4*)(h0d + (size_t)(b0 + row) * H + j);
                float4 cv = *(const float4*)(c0d + (size_t)(b0 + row) * H + j);
                Acs[(j + 0) * 64 + row] = hv.x; Acs[(j + 1) * 64 + row] = hv.y;
                Acs[(j + 2) * 64 + row] = hv.z; Acs[(j + 3) * 64 + row] = hv.w;
                Acs[(64 + j + 0) * 64 + row] = cv.x; Acs[(64 + j + 1) * 64 + row] = cv.y;
                Acs[(64 + j + 2) * 64 + row] = cv.z; Acs[(64 + j + 3) * 64 + row] = cv.w;
            }
        }
        ull bp2[4];
        {
            float bres[8];
#pragma unroll
            for (int g = 0; g < 4; g++) {
                bres[g]     = dec_bih[g * H + j0]     + dec_bhh[g * H + j0];
                bres[4 + g] = dec_bih[g * H + j0 + 1] + dec_bhh[g * H + j0 + 1];
            }
            bp2[0] = pack2(bres[0], bres[1]); bp2[1] = pack2(bres[2], bres[3]);
            bp2[2] = pack2(bres[4], bres[5]); bp2[3] = pack2(bres[6], bres[7]);
        }
        __syncthreads();

        for (int t = 0; t < L; t++) {
            // ---- Phase A: q = [h|c] @ Wq + b1 ----
            {
                ull qa[4][2];
#pragma unroll
                for (int p = 0; p < 4; p++) { qa[p][0] = 0; qa[p][1] = 0; }
#pragma unroll 4
                for (int k = 0; k < 128; k++) {
                    const float* ap = Acs + k * 64;
                    ulonglong2 hA = *(const ulonglong2*)(ap + r0);
                    ulonglong2 hB = *(const ulonglong2*)(ap + r0 + 4);
                    float2 w = *(const float2*)(Wq + k * H + j0);
                    ull w0 = dup2(w.x), w1d = dup2(w.y);
                    qa[0][0] = fma2(hA.x, w0, qa[0][0]); qa[1][0] = fma2(hA.y, w0, qa[1][0]);
                    qa[2][0] = fma2(hB.x, w0, qa[2][0]); qa[3][0] = fma2(hB.y, w0, qa[3][0]);
                    qa[0][1] = fma2(hA.x, w1d, qa[0][1]); qa[1][1] = fma2(hA.y, w1d, qa[1][1]);
                    qa[2][1] = fma2(hB.x, w1d, qa[2][1]); qa[3][1] = fma2(hB.y, w1d, qa[3][1]);
                }
                float b1a = b1_s[j0], b1b = b1_s[j0 + 1];
#pragma unroll
                for (int p = 0; p < 4; p++) {
                    float2 u0 = unpack2(qa[p][0]), u1 = unpack2(qa[p][1]);
                    q_s[(r0 + 2 * p) * QSTR + j0]         = u0.x + b1a;
                    q_s[(r0 + 2 * p + 1) * QSTR + j0]     = u0.y + b1a;
                    q_s[(r0 + 2 * p) * QSTR + j0 + 1]     = u1.x + b1b;
                    q_s[(r0 + 2 * p + 1) * QSTR + j0 + 1] = u1.y + b1b;
                }
            }
            __syncthreads();

            // ---- Phase B: scores -> softmax -> ctx ----
            {
                float qv[16], w2v[16];
                const float* qrow = q_s + rowq * QSTR + q4 * 16;
                const float* w2p = w2_s + q4 * 16;
#pragma unroll
                for (int i = 0; i < 16; i++) { qv[i] = qrow[i]; w2v[i] = w2p[i]; }
                const float* prep = g_pre + (size_t)(b0 + rowq) * L * H + q4 * 16;
                float at[L];
#pragma unroll
                for (int l = 0; l < L; l++) {
                    float s = 0.f;
#pragma unroll
                    for (int i = 0; i < 16; i += 4) {
                        float4 pv = *(const float4*)(prep + l * H + i);
                        s = fmaf(tanh_ap(pv.x + qv[i + 0]), w2v[i + 0], s);
                        s = fmaf(tanh_ap(pv.y + qv[i + 1]), w2v[i + 1], s);
                        s = fmaf(tanh_ap(pv.z + qv[i + 2]), w2v[i + 2], s);
                        s = fmaf(tanh_ap(pv.w + qv[i + 3]), w2v[i + 3], s);
                    }
                    s += __shfl_xor_sync(0xFFFFFFFFu, s, 1);
                    s += __shfl_xor_sync(0xFFFFFFFFu, s, 2);
                    at[l] = s;
                }
                float m = at[0];
#pragma unroll
                for (int l = 1; l < L; l++) m = fmaxf(m, at[l]);
                float ssum = 0.f;
#pragma unroll
                for (int l = 0; l < L; l++) { at[l] = __expf(at[l] - m); ssum += at[l]; }
                float inv = __fdividef(1.f, ssum);
#pragma unroll
                for (int l = 0; l < L; l++) at[l] *= inv;

                float4 cac[4];
#pragma unroll
                for (int i = 0; i < 4; i++) cac[i] = make_float4(0.f, 0.f, 0.f, 0.f);
                const float* xep = g_xenc + (size_t)(b0 + rowq) * L * H + q4 * 16;
#pragma unroll
                for (int l = 0; l < L; l++) {
#pragma unroll
                    for (int i = 0; i < 4; i++) {
                        float4 xv = *(const float4*)(xep + l * H + i * 4);
                        cac[i].x = fmaf(at[l], xv.x, cac[i].x);
                        cac[i].y = fmaf(at[l], xv.y, cac[i].y);
                        cac[i].z = fmaf(at[l], xv.z, cac[i].z);
                        cac[i].w = fmaf(at[l], xv.w, cac[i].w);
                    }
                }
#pragma unroll
                for (int i = 0; i < 4; i++)
                    *(float4*)(ctx_s + rowq * CSTR + q4 * 16 + i * 4) = cac[i];
            }
            __syncthreads();

            // ---- Phase E: y_tilde = [ctx|y_t] @ fc_w^T + fc_b ----
            for (int u = tid; u < 5 * 64; u += NTHR) {
                int row = u & 63, o = u >> 6;
                float s = fcb_s[o];
                const float* fw = fcw_s + o * 72;
                const float* cx = ctx_s + row * CSTR;
#pragma unroll 8
                for (int k = 0; k < 64; k++) s = fmaf(fw[k], cx[k], s);
                const float* yh = y_hist + ((size_t)(b0 + row) * L + t) * OUT;
#pragma unroll
                for (int k = 0; k < OUT; k++) s = fmaf(fw[64 + k], yh[k], s);
                As2[o * 64 + row] = s;
            }
            __syncthreads();

            // ---- Phase F: gates (k = 5 + 64) ----
            ull acc[8][4];
#pragma unroll
            for (int i = 0; i < 8; i++)
#pragma unroll
                for (int p = 0; p < 4; p++) acc[i][p] = bp2[p];
#pragma unroll
            for (int k = 0; k < 5; k++) {
                const float* ap = As2 + k * 64;
                float4 a0 = *(const float4*)(ap + r0);
                float4 a1 = *(const float4*)(ap + r0 + 4);
                const ulonglong2* vp = (const ulonglong2*)(Wdec + k * G4 + jc * 8);
                ulonglong2 vA = vp[0], vB = vp[1];
                float av[8] = {a0.x, a0.y, a0.z, a0.w, a1.x, a1.y, a1.z, a1.w};
#pragma unroll
                for (int i = 0; i < 8; i++) {
                    ull ad = dup2(av[i]);
                    acc[i][0] = fma2(ad, vA.x, acc[i][0]);
                    acc[i][1] = fma2(ad, vA.y, acc[i][1]);
                    acc[i][2] = fma2(ad, vB.x, acc[i][2]);
                    acc[i][3] = fma2(ad, vB.y, acc[i][3]);
                }
            }
#pragma unroll 4
            for (int k = 0; k < 64; k++) {
                const float* ap = Acs + k * 64;
                float4 a0 = *(const float4*)(ap + r0);
                float4 a1 = *(const float4*)(ap + r0 + 4);
                const ulonglong2* vp = (const ulonglong2*)(Wdec + (5 + k) * G4 + jc * 8);
                ulonglong2 vA = vp[0], vB = vp[1];
                float av[8] = {a0.x, a0.y, a0.z, a0.w, a1.x, a1.y, a1.z, a1.w};
#pragma unroll
                for (int i = 0; i < 8; i++) {
                    ull ad = dup2(av[i]);
                    acc[i][0] = fma2(ad, vA.x, acc[i][0]);
                    acc[i][1] = fma2(ad, vA.y, acc[i][1]);
                    acc[i][2] = fma2(ad, vB.x, acc[i][2]);
                    acc[i][3] = fma2(ad, vB.y, acc[i][3]);
                }
            }
            __syncthreads();   // old-h reads done

            // ---- Phase G: LSTM cell, update h/c ----
#pragma unroll
            for (int i = 0; i < 8; i++) {
                float2 u0 = unpack2(acc[i][0]), u1 = unpack2(acc[i][1]);
                float2 u2 = unpack2(acc[i][2]), u3 = unpack2(acc[i][3]);
                float co0 = Acs[(64 + j0) * 64 + r0 + i];
                float co1 = Acs[(64 + j0 + 1) * 64 + r0 + i];
                float cn0 = sigf(u0.y) * co0 + sigf(u0.x) * tanh_acc(u1.x);
                float hn0 = sigf(u1.y) * tanh_acc(cn0);
                float cn1 = sigf(u2.y) * co1 + sigf(u2.x) * tanh_acc(u3.x);
                float hn1 = sigf(u3.y) * tanh_acc(cn1);
                Acs[(j0) * 64 + r0 + i]          = hn0;
                Acs[(j0 + 1) * 64 + r0 + i]      = hn1;
                Acs[(64 + j0) * 64 + r0 + i]     = cn0;
                Acs[(64 + j0 + 1) * 64 + r0 + i] = cn1;
            }
            __syncthreads();
        }

        // ---- out = [h | ctx] @ fcout_w^T + fcout_b ----
        for (int u = tid; u < 5 * 64; u += NTHR) {
            int row = u & 63, o = u >> 6;
            float s = fob_s[o];
            const float* fw = fow_s + o * 128;
#pragma unroll 8
            for (int k = 0; k < 64; k++) s = fmaf(fw[k], Acs[k * 64 + row], s);
            const float* cx = ctx_s + row * CSTR;
#pragma unroll 8
            for (int k = 0; k < 64; k++) s = fmaf(fw[64 + k], cx[k], s);
            out[(size_t)(b0 + row) * OUT + o] = s;
        }
    }
}

// =============================================================
// launcher
// =============================================================
extern "C" void kernel_launch(void* const* d_in, const int* in_sizes, int n_in,
                              void* d_out, int out_size) {
    const float* x           = (const float*)d_in[0];
    const float* y_hist      = (const float*)d_in[1];
    const float* h0_enc      = (const float*)d_in[2];
    const float* c0_enc      = (const float*)d_in[3];
    const float* h0_dec      = (const float*)d_in[4];
    const float* c0_dec      = (const float*)d_in[5];
    const float* enc_attn_w  = (const float*)d_in[6];
    // d_in[7] enc_attn_b: softmax-shift-invariant, unused
    const float* enc_Wih     = (const float*)d_in[8];
    const float* enc_Whh     = (const float*)d_in[9];
    const float* enc_bih     = (const float*)d_in[10];
    const float* enc_bhh     = (const float*)d_in[11];
    const float* dec_attn_w1 = (const float*)d_in[12];
    const float* dec_attn_b1 = (const float*)d_in[13];
    const float* dec_attn_w2 = (const float*)d_in[14];
    // d_in[15] dec_attn_b2: softmax-shift-invariant, unused
    const float* dec_Wih     = (const float*)d_in[16];
    const float* dec_Whh     = (const float*)d_in[17];
    const float* dec_bih     = (const float*)d_in[18];
    const float* dec_bhh     = (const float*)d_in[19];
    const float* fc_w        = (const float*)d_in[20];
    const float* fc_b        = (const float*)d_in[21];
    const float* fcout_w     = (const float*)d_in[22];
    const float* fcout_b     = (const float*)d_in[23];
    float* out = (float*)d_out;

    const int gx_smem = (128 * ASTR + 16 * G4) * 4;                     // 49152 B
    const int enc_sm  = (64 * G4 + 64 * ASTR + 64 * 64) * 4;            // 98304 B
    const int dec_sm  = (69 * G4 + 128 * H + 128 * 64 + 5 * 64 +
                         64 * QSTR + 64 * CSTR + 64 + 64 +
                         5 * 72 + 8 + 5 * 128 + 8) * 4;                 // ~176.9 KB
    const int net_smem = (enc_sm > dec_sm) ? enc_sm : dec_sm;
    cudaFuncSetAttribute(k_gatex, cudaFuncAttributeMaxDynamicSharedMemorySize, gx_smem);
    cudaFuncSetAttribute(k_net, cudaFuncAttributeMaxDynamicSharedMemorySize, net_smem);

    const int repack_n = 192 * G4 + 69 * G4 + 128 * H;
    k_repack<<<(repack_n + 255) / 256, 256>>>(
        enc_Wih, enc_Whh, dec_Wih, dec_Whh, dec_attn_w1);
    k_atten<<<B / 64, NTHR>>>(x, enc_attn_w);
    k_gatex<<<(B * L) / 64, NTHR, gx_smem>>>(x, enc_bih, enc_bhh);
    k_net<<<B / TILE, NTHR, net_smem>>>(
        h0_enc, c0_enc, dec_attn_w1,
        y_hist, h0_dec, c0_dec, dec_attn_b1, dec_attn_w2,
        dec_bih, dec_bhh, fc_w, fc_b, fcout_w, fcout_b, out);
}

// round 10
// speedup vs baseline: 1.2931x; 1.2931x over previous
#include <cuda_runtime.h>

typedef unsigned long long ull;

#define B 8192
#define L 10
#define D 128
#define H 64
#define G4 256          // 4*H
#define OUT 5
#define TILE 64
#define NTHR 512
#define QSTR 68
#define CSTR 68

// ------------------- global scratch -------------------
__device__ float g_xenc[(size_t)B * L * H];   // encoder hidden sequence
__device__ float g_pre[(size_t)B * L * H];    // x_enc @ W1x^T
__device__ float g_Wenc[192 * G4];            // [k][j*4+g]  k: 0..127 Wih, 128..191 Whh
__device__ float g_Wdec[69 * G4];             // [k][j*4+g]  k: 0..4 Wih, 5..68 Whh
__device__ float g_Wq[128 * H];               // [k][hh]     k: 0..63 W1h, 64..127 W1c

// ------------------- helpers -------------------
__device__ __forceinline__ ull pack2(float x, float y) {
    ull r; asm("mov.b64 %0, {%1, %2};" : "=l"(r) : "f"(x), "f"(y)); return r;
}
__device__ __forceinline__ ull dup2(float x) { return pack2(x, x); }
__device__ __forceinline__ float2 unpack2(ull v) {
    float2 f; asm("mov.b64 {%0, %1}, %2;" : "=f"(f.x), "=f"(f.y) : "l"(v)); return f;
}
__device__ __forceinline__ ull fma2(ull a, ull b, ull c) {
    ull d; asm("fma.rn.f32x2 %0, %1, %2, %3;" : "=l"(d) : "l"(a), "l"(b), "l"(c)); return d;
}
__device__ __forceinline__ float sigf(float x) {
    return __fdividef(1.f, 1.f + __expf(-x));
}
__device__ __forceinline__ float tanh_acc(float x) {
    return 1.f - __fdividef(2.f, __expf(2.f * x) + 1.f);
}
__device__ __forceinline__ float tanh_ap(float x) {
    float y; asm("tanh.approx.f32 %0, %1;" : "=f"(y) : "f"(x)); return y;
}

// =============================================================
// K0: repack weights
// =============================================================
__global__ void k_repack(const float* __restrict__ eWih, const float* __restrict__ eWhh,
                         const float* __restrict__ dWih, const float* __restrict__ dWhh,
                         const float* __restrict__ w1) {
    int idx = blockIdx.x * 256 + threadIdx.x;
    if (idx < 192 * G4) {
        int k = idx >> 8, c4 = idx & 255, j = c4 >> 2, g = c4 & 3;
        g_Wenc[idx] = (k < 128) ? eWih[(g * H + j) * D + k]
                                : eWhh[(g * H + j) * H + (k - 128)];
        return;
    }
    idx -= 192 * G4;
    if (idx < 69 * G4) {
        int k = idx >> 8, c4 = idx & 255, j = c4 >> 2, g = c4 & 3;
        g_Wdec[idx] = (k < 5) ? dWih[(g * H + j) * OUT + k]
                              : dWhh[(g * H + j) * H + (k - 5)];
        return;
    }
    idx -= 69 * G4;
    if (idx < 128 * H) {
        int k = idx >> 6, hh = idx & 63;
        g_Wq[idx] = (k < 64) ? w1[hh * 192 + k] : w1[hh * 192 + 64 + (k - 64)];
    }
}

// =============================================================
// K1: fused network, 512 threads/CTA (16 warps), 64 rows/CTA.
// =============================================================
__global__ __launch_bounds__(NTHR, 1) void k_net(
    const float* __restrict__ x, const float* __restrict__ h0,
    const float* __restrict__ c0, const float* __restrict__ bih,
    const float* __restrict__ bhh, const float* __restrict__ enc_attn_w,
    const float* __restrict__ w1,
    const float* __restrict__ y_hist, const float* __restrict__ h0d,
    const float* __restrict__ c0d,
    const float* __restrict__ dec_attn_b1, const float* __restrict__ dec_attn_w2,
    const float* __restrict__ dec_bih, const float* __restrict__ dec_bhh,
    const float* __restrict__ fc_w, const float* __restrict__ fc_b,
    const float* __restrict__ fcout_w, const float* __restrict__ fcout_b,
    float* __restrict__ out) {
    extern __shared__ float sm[];

    const int tid = threadIdx.x;
    const int rt = tid & 15, jc = tid >> 4;      // 16 row-threads x 32 col-threads
    const int r0 = rt * 4, j0 = jc * 2;          // 4 rows, col-pair base
    const int b0 = blockIdx.x * TILE;
    const int rowp = tid >> 3, dg = tid & 7;     // 64 rows x 8 d-groups (staging / Phase B)

    // =========================================================
    // ENCODER PHASE — smem: As[192][64], Bs0/Bs1[32][256], Ws1x[64][64]
    // =========================================================
    {
        float* As   = sm;                    // 48 KB
        float* Bs0  = As + 192 * 64;         // 32 KB
        float* Bs1  = Bs0 + 32 * G4;         // 32 KB
        float* Ws1x = Bs1 + 32 * G4;         // 16 KB

        // stage Ws1x[e][hh] = W1x[hh][e]
        for (int i = tid; i < 64 * 64; i += NTHR) {
            int e = i >> 6, hh = i & 63;
            Ws1x[e * 64 + hh] = w1[hh * 192 + 128 + e];
        }

        // ---- attention weights in registers (exact; 16 d per thread) ----
        float4 at4[4];
        {
            float wx[L];
#pragma unroll
            for (int l = 0; l < L; l++) wx[l] = __ldg(enc_attn_w + 2 * H + l);
#pragma unroll
            for (int i = 0; i < 4; i++) at4[i] = make_float4(0.f, 0.f, 0.f, 0.f);
            const float* xp = x + (size_t)(b0 + rowp) * L * D + dg * 16;
#pragma unroll
            for (int l = 0; l < L; l++) {
#pragma unroll
                for (int i = 0; i < 4; i++) {
                    float4 v = *(const float4*)(xp + l * D + i * 4);
                    at4[i].x = fmaf(v.x, wx[l], at4[i].x);
                    at4[i].y = fmaf(v.y, wx[l], at4[i].y);
                    at4[i].z = fmaf(v.z, wx[l], at4[i].z);
                    at4[i].w = fmaf(v.w, wx[l], at4[i].w);
                }
            }
            float m = -1e30f;
#pragma unroll
            for (int i = 0; i < 4; i++)
                m = fmaxf(m, fmaxf(fmaxf(at4[i].x, at4[i].y), fmaxf(at4[i].z, at4[i].w)));
            m = fmaxf(m, __shfl_xor_sync(0xFFFFFFFFu, m, 1));
            m = fmaxf(m, __shfl_xor_sync(0xFFFFFFFFu, m, 2));
            m = fmaxf(m, __shfl_xor_sync(0xFFFFFFFFu, m, 4));
            float s = 0.f;
#pragma unroll
            for (int i = 0; i < 4; i++) {
                at4[i].x = __expf(at4[i].x - m); at4[i].y = __expf(at4[i].y - m);
                at4[i].z = __expf(at4[i].z - m); at4[i].w = __expf(at4[i].w - m);
                s += at4[i].x + at4[i].y + at4[i].z + at4[i].w;
            }
            s += __shfl_xor_sync(0xFFFFFFFFu, s, 1);
            s += __shfl_xor_sync(0xFFFFFFFFu, s, 2);
            s += __shfl_xor_sync(0xFFFFFFFFu, s, 4);
            float inv = __fdividef(1.f, s);
#pragma unroll
            for (int i = 0; i < 4; i++) {
                at4[i].x *= inv; at4[i].y *= inv; at4[i].z *= inv; at4[i].w *= inv;
            }
        }

        // ---- stage h0 transposed into As[128..191] ----
        {
            const float* hp = h0 + (size_t)(b0 + rowp) * H + dg * 8;
            float4 v0 = *(const float4*)(hp);
            float4 v1 = *(const float4*)(hp + 4);
            int j = 128 + dg * 8;
            As[(j + 0) * 64 + rowp] = v0.x; As[(j + 1) * 64 + rowp] = v0.y;
            As[(j + 2) * 64 + rowp] = v0.z; As[(j + 3) * 64 + rowp] = v0.w;
            As[(j + 4) * 64 + rowp] = v1.x; As[(j + 5) * 64 + rowp] = v1.y;
            As[(j + 6) * 64 + rowp] = v1.z; As[(j + 7) * 64 + rowp] = v1.w;
        }
        // ---- cell state + packed bias pairs ----
        float cr0[4], cr1[4];
        ull bp[4];
#pragma unroll
        for (int p = 0; p < 4; p++) {
            int j = j0 + (p >> 1), g0 = (p & 1) * 2;
            bp[p] = pack2(bih[g0 * H + j] + bhh[g0 * H + j],
                          bih[(g0 + 1) * H + j] + bhh[(g0 + 1) * H + j]);
        }
#pragma unroll
        for (int i = 0; i < 4; i++) {
            cr0[i] = c0[(size_t)(b0 + r0 + i) * H + j0];
            cr1[i] = c0[(size_t)(b0 + r0 + i) * H + j0 + 1];
        }
        __syncthreads();

        for (int t = 0; t < L; t++) {
            // prefetch weight chunk 0 (32 k x 256)
            const float4* wp0 = (const float4*)g_Wenc + tid * 4;
            float4 f0 = wp0[0], f1 = wp0[1], f2 = wp0[2], f3 = wp0[3];

            // stage wi = at*x_t transposed into As[0..127]
            {
                const float* xp = x + ((size_t)(b0 + rowp) * L + t) * D + dg * 16;
#pragma unroll
                for (int i = 0; i < 4; i++) {
                    float4 xv = *(const float4*)(xp + i * 4);
                    int k = dg * 16 + i * 4;
                    As[(k + 0) * 64 + rowp] = xv.x * at4[i].x;
                    As[(k + 1) * 64 + rowp] = xv.y * at4[i].y;
                    As[(k + 2) * 64 + rowp] = xv.z * at4[i].z;
                    As[(k + 3) * 64 + rowp] = xv.w * at4[i].w;
                }
            }
            {
                float4* b4 = (float4*)Bs0 + tid * 4;
                b4[0] = f0; b4[1] = f1; b4[2] = f2; b4[3] = f3;
            }
            __syncthreads();

            // ---- gate GEMM: 4 rows x 8 cols per thread, 6 chunks ----
            ull acc[4][4];
#pragma unroll
            for (int i = 0; i < 4; i++)
#pragma unroll
                for (int p = 0; p < 4; p++) acc[i][p] = bp[p];

            for (int kb = 0; kb < 6; kb++) {
                const float* Bsc = (kb & 1) ? Bs1 : Bs0;
                float4 n0, n1, n2, n3;
                if (kb < 5) {
                    const float4* wp = (const float4*)(g_Wenc + (kb + 1) * 32 * G4) + tid * 4;
                    n0 = wp[0]; n1 = wp[1]; n2 = wp[2]; n3 = wp[3];
                }
#pragma unroll
                for (int kk = 0; kk < 32; kk++) {
                    const float* ap = As + (kb * 32 + kk) * 64;
                    float4 a = *(const float4*)(ap + r0);
                    const ulonglong2* vp = (const ulonglong2*)(Bsc + kk * G4 + jc * 8);
                    ulonglong2 vA = vp[0], vB = vp[1];
                    float av[4] = {a.x, a.y, a.z, a.w};
#pragma unroll
                    for (int i = 0; i < 4; i++) {
                        ull ad = dup2(av[i]);
                        acc[i][0] = fma2(ad, vA.x, acc[i][0]);
                        acc[i][1] = fma2(ad, vA.y, acc[i][1]);
                        acc[i][2] = fma2(ad, vB.x, acc[i][2]);
                        acc[i][3] = fma2(ad, vB.y, acc[i][3]);
                    }
                }
                if (kb < 5) {
                    float* Bn = (kb & 1) ? Bs0 : Bs1;
                    float4* b4 = (float4*)Bn + tid * 4;
                    b4[0] = n0; b4[1] = n1; b4[2] = n2; b4[3] = n3;
                    __syncthreads();
                }
            }
            __syncthreads();   // all GEMM reads done

            // ---- activations (4 rows x 2 cols) ----
#pragma unroll
            for (int i = 0; i < 4; i++) {
                float2 u0 = unpack2(acc[i][0]), u1 = unpack2(acc[i][1]);
                float2 u2 = unpack2(acc[i][2]), u3 = unpack2(acc[i][3]);
                float cn0 = sigf(u0.y) * cr0[i] + sigf(u0.x) * tanh_acc(u1.x);
                float hn0 = sigf(u1.y) * tanh_acc(cn0);
                float cn1 = sigf(u2.y) * cr1[i] + sigf(u2.x) * tanh_acc(u3.x);
                float hn1 = sigf(u3.y) * tanh_acc(cn1);
                cr0[i] = cn0; cr1[i] = cn1;
                As[(128 + j0) * 64 + r0 + i]     = hn0;
                As[(128 + j0 + 1) * 64 + r0 + i] = hn1;
                *(float2*)(g_xenc + ((size_t)(b0 + r0 + i) * L + t) * H + j0) =
                    make_float2(hn0, hn1);
            }
            __syncthreads();   // h visible

            // ---- fused pre-GEMM: pre = h @ W1x^T (4 rows x 2 cols) ----
            {
                ull p0c0 = 0, p1c0 = 0, p0c1 = 0, p1c1 = 0;
#pragma unroll 8
                for (int e = 0; e < 64; e++) {
                    const float* hp = As + (128 + e) * 64;
                    ulonglong2 hA = *(const ulonglong2*)(hp + r0);
                    float2 w = *(const float2*)(Ws1x + e * 64 + j0);
                    ull w0 = dup2(w.x), w1d = dup2(w.y);
                    p0c0 = fma2(hA.x, w0, p0c0);  p1c0 = fma2(hA.y, w0, p1c0);
                    p0c1 = fma2(hA.x, w1d, p0c1); p1c1 = fma2(hA.y, w1d, p1c1);
                }
                float2 a0 = unpack2(p0c0), a1 = unpack2(p1c0);
                float2 c0v = unpack2(p0c1), c1v = unpack2(p1c1);
                float* pb = g_pre + ((size_t)(b0 + r0) * L + t) * H + j0;
                const size_t rs = (size_t)L * H;
                *(float2*)(pb + 0 * rs) = make_float2(a0.x, c0v.x);
                *(float2*)(pb + 1 * rs) = make_float2(a0.y, c0v.y);
                *(float2*)(pb + 2 * rs) = make_float2(a1.x, c1v.x);
                *(float2*)(pb + 3 * rs) = make_float2(a1.y, c1v.y);
            }
            // next staging writes As[0..127], pre reads As[128..191] — disjoint
        }
    }
    __syncthreads();   // encoder smem dead; repartition for decoder

    // =========================================================
    // DECODER PHASE
    // =========================================================
    {
        float* Wdec  = sm;                    // [69][256]
        float* Wq    = Wdec + 69 * G4;        // [128][64]
        float* Acs   = Wq + 128 * H;          // [128][64]: 0..63 h, 64..127 c
        float* As2   = Acs + 128 * 64;        // [5][64]
        float* q_s   = As2 + 5 * 64;          // [64][QSTR]
        float* ctx_s = q_s + 64 * QSTR;       // [64][CSTR]
        float* w2_s  = ctx_s + 64 * CSTR;     // [64]
        float* b1_s  = w2_s + 64;             // [64]
        float* fcw_s = b1_s + 64;             // [5][72]
        float* fcb_s = fcw_s + 5 * 72;        // [8]
        float* fow_s = fcb_s + 8;             // [5][128]
        float* fob_s = fow_s + 5 * 128;       // [8]

        const int rowq = tid >> 3, q8 = tid & 7;

        for (int i = tid; i < 69 * G4; i += NTHR)  Wdec[i] = g_Wdec[i];
        for (int i = tid; i < 128 * H; i += NTHR)  Wq[i]   = g_Wq[i];
        if (tid < 64) { w2_s[tid] = dec_attn_w2[tid]; b1_s[tid] = dec_attn_b1[tid]; }
        for (int i = tid; i < 5 * 69; i += NTHR) {
            int o = i / 69, k = i % 69;
            fcw_s[o * 72 + k] = fc_w[i];
        }
        for (int i = tid; i < 5 * 128; i += NTHR) fow_s[i] = fcout_w[i];
        if (tid < 5) { fcb_s[tid] = fc_b[tid]; fob_s[tid] = fcout_b[tid]; }

        {   // h0/c0 transposed (8 cols per thread)
            const float* hp = h0d + (size_t)(b0 + rowp) * H + dg * 8;
            const float* cp = c0d + (size_t)(b0 + rowp) * H + dg * 8;
            float4 h0v = *(const float4*)(hp), h1v = *(const float4*)(hp + 4);
            float4 c0v = *(const float4*)(cp), c1v = *(const float4*)(cp + 4);
            int j = dg * 8;
            Acs[(j + 0) * 64 + rowp] = h0v.x; Acs[(j + 1) * 64 + rowp] = h0v.y;
            Acs[(j + 2) * 64 + rowp] = h0v.z; Acs[(j + 3) * 64 + rowp] = h0v.w;
            Acs[(j + 4) * 64 + rowp] = h1v.x; Acs[(j + 5) * 64 + rowp] = h1v.y;
            Acs[(j + 6) * 64 + rowp] = h1v.z; Acs[(j + 7) * 64 + rowp] = h1v.w;
            Acs[(64 + j + 0) * 64 + rowp] = c0v.x; Acs[(64 + j + 1) * 64 + rowp] = c0v.y;
            Acs[(64 + j + 2) * 64 + rowp] = c0v.z; Acs[(64 + j + 3) * 64 + rowp] = c0v.w;
            Acs[(64 + j + 4) * 64 + rowp] = c1v.x; Acs[(64 + j + 5) * 64 + rowp] = c1v.y;
            Acs[(64 + j + 6) * 64 + rowp] = c1v.z; Acs[(64 + j + 7) * 64 + rowp] = c1v.w;
        }
        ull bp2[4];
#pragma unroll
        for (int p = 0; p < 4; p++) {
            int j = j0 + (p >> 1), g0 = (p & 1) * 2;
            bp2[p] = pack2(dec_bih[g0 * H + j] + dec_bhh[g0 * H + j],
                           dec_bih[(g0 + 1) * H + j] + dec_bhh[(g0 + 1) * H + j]);
        }
        __syncthreads();

        for (int t = 0; t < L; t++) {
            // ---- Phase A: q = [h|c] @ Wq + b1 (4 rows x 2 cols) ----
            {
                ull qa00 = 0, qa10 = 0, qa01 = 0, qa11 = 0;
#pragma unroll 4
                for (int k = 0; k < 128; k++) {
                    const float* ap = Acs + k * 64;
                    ulonglong2 hA = *(const ulonglong2*)(ap + r0);
                    float2 w = *(const float2*)(Wq + k * H + j0);
                    ull w0 = dup2(w.x), w1d = dup2(w.y);
                    qa00 = fma2(hA.x, w0, qa00);  qa10 = fma2(hA.y, w0, qa10);
                    qa01 = fma2(hA.x, w1d, qa01); qa11 = fma2(hA.y, w1d, qa11);
                }
                float b1a = b1_s[j0], b1b = b1_s[j0 + 1];
                float2 u00 = unpack2(qa00), u10 = unpack2(qa10);
                float2 u01 = unpack2(qa01), u11 = unpack2(qa11);
                q_s[(r0 + 0) * QSTR + j0]     = u00.x + b1a;
                q_s[(r0 + 1) * QSTR + j0]     = u00.y + b1a;
                q_s[(r0 + 2) * QSTR + j0]     = u10.x + b1a;
                q_s[(r0 + 3) * QSTR + j0]     = u10.y + b1a;
                q_s[(r0 + 0) * QSTR + j0 + 1] = u01.x + b1b;
                q_s[(r0 + 1) * QSTR + j0 + 1] = u01.y + b1b;
                q_s[(r0 + 2) * QSTR + j0 + 1] = u11.x + b1b;
                q_s[(r0 + 3) * QSTR + j0 + 1] = u11.y + b1b;
            }
            __syncthreads();

            // ---- Phase B: scores -> softmax -> ctx (8 lanes per row) ----
            {
                float qv[8], w2v[8];
                const float* qrow = q_s + rowq * QSTR + q8 * 8;
                const float* w2p = w2_s + q8 * 8;
#pragma unroll
                for (int i = 0; i < 8; i++) { qv[i] = qrow[i]; w2v[i] = w2p[i]; }
                const float* prep = g_pre + (size_t)(b0 + rowq) * L * H + q8 * 8;
                float at[L];
#pragma unroll
                for (int l = 0; l < L; l++) {
                    float4 p0 = *(const float4*)(prep + l * H);
                    float4 p1 = *(const float4*)(prep + l * H + 4);
                    float s;
                    s = tanh_ap(p0.x + qv[0]) * w2v[0];
                    s = fmaf(tanh_ap(p0.y + qv[1]), w2v[1], s);
                    s = fmaf(tanh_ap(p0.z + qv[2]), w2v[2], s);
                    s = fmaf(tanh_ap(p0.w + qv[3]), w2v[3], s);
                    s = fmaf(tanh_ap(p1.x + qv[4]), w2v[4], s);
                    s = fmaf(tanh_ap(p1.y + qv[5]), w2v[5], s);
                    s = fmaf(tanh_ap(p1.z + qv[6]), w2v[6], s);
                    s = fmaf(tanh_ap(p1.w + qv[7]), w2v[7], s);
                    s += __shfl_xor_sync(0xFFFFFFFFu, s, 1);
                    s += __shfl_xor_sync(0xFFFFFFFFu, s, 2);
                    s += __shfl_xor_sync(0xFFFFFFFFu, s, 4);
                    at[l] = s;
                }
                float m = at[0];
#pragma unroll
                for (int l = 1; l < L; l++) m = fmaxf(m, at[l]);
                float ssum = 0.f;
#pragma unroll
                for (int l = 0; l < L; l++) { at[l] = __expf(at[l] - m); ssum += at[l]; }
                float inv = __fdividef(1.f, ssum);
#pragma unroll
                for (int l = 0; l < L; l++) at[l] *= inv;

                float4 c0a = make_float4(0.f, 0.f, 0.f, 0.f);
                float4 c1a = make_float4(0.f, 0.f, 0.f, 0.f);
                const float* xep = g_xenc + (size_t)(b0 + rowq) * L * H + q8 * 8;
#pragma unroll
                for (int l = 0; l < L; l++) {
                    float4 x0 = *(const float4*)(xep + l * H);
                    float4 x1 = *(const float4*)(xep + l * H + 4);
                    c0a.x = fmaf(at[l], x0.x, c0a.x); c0a.y = fmaf(at[l], x0.y, c0a.y);
                    c0a.z = fmaf(at[l], x0.z, c0a.z); c0a.w = fmaf(at[l], x0.w, c0a.w);
                    c1a.x = fmaf(at[l], x1.x, c1a.x); c1a.y = fmaf(at[l], x1.y, c1a.y);
                    c1a.z = fmaf(at[l], x1.z, c1a.z); c1a.w = fmaf(at[l], x1.w, c1a.w);
                }
                *(float4*)(ctx_s + rowq * CSTR + q8 * 8)     = c0a;
                *(float4*)(ctx_s + rowq * CSTR + q8 * 8 + 4) = c1a;
            }
            __syncthreads();

            // ---- Phase E: y_tilde = [ctx|y_t] @ fc_w^T + fc_b ----
            if (tid < 5 * 64) {
                int row = tid & 63, o = tid >> 6;
                float s = fcb_s[o];
                const float* fw = fcw_s + o * 72;
                const float* cx = ctx_s + row * CSTR;
#pragma unroll 8
                for (int k = 0; k < 64; k++) s = fmaf(fw[k], cx[k], s);
                const float* yh = y_hist + ((size_t)(b0 + row) * L + t) * OUT;
#pragma unroll
                for (int k = 0; k < OUT; k++) s = fmaf(fw[64 + k], yh[k], s);
                As2[o * 64 + row] = s;
            }
            __syncthreads();

            // ---- Phase F: gates (4 rows x 8 cols, k = 5 + 64) ----
            ull acc[4][4];
#pragma unroll
            for (int i = 0; i < 4; i++)
#pragma unroll
                for (int p = 0; p < 4; p++) acc[i][p] = bp2[p];
#pragma unroll
            for (int k = 0; k < 5; k++) {
                const float* ap = As2 + k * 64;
                float4 a = *(const float4*)(ap + r0);
                const ulonglong2* vp = (const ulonglong2*)(Wdec + k * G4 + jc * 8);
                ulonglong2 vA = vp[0], vB = vp[1];
                float av[4] = {a.x, a.y, a.z, a.w};
#pragma unroll
                for (int i = 0; i < 4; i++) {
                    ull ad = dup2(av[i]);
                    acc[i][0] = fma2(ad, vA.x, acc[i][0]);
                    acc[i][1] = fma2(ad, vA.y, acc[i][1]);
                    acc[i][2] = fma2(ad, vB.x, acc[i][2]);
                    acc[i][3] = fma2(ad, vB.y, acc[i][3]);
                }
            }
#pragma unroll 8
            for (int k = 0; k < 64; k++) {
                const float* ap = Acs + k * 64;
                float4 a = *(const float4*)(ap + r0);
                const ulonglong2* vp = (const ulonglong2*)(Wdec + (5 + k) * G4 + jc * 8);
                ulonglong2 vA = vp[0], vB = vp[1];
                float av[4] = {a.x, a.y, a.z, a.w};
#pragma unroll
                for (int i = 0; i < 4; i++) {
                    ull ad = dup2(av[i]);
                    acc[i][0] = fma2(ad, vA.x, acc[i][0]);
                    acc[i][1] = fma2(ad, vA.y, acc[i][1]);
                    acc[i][2] = fma2(ad, vB.x, acc[i][2]);
                    acc[i][3] = fma2(ad, vB.y, acc[i][3]);
                }
            }
            __syncthreads();   // old-h reads done

            // ---- Phase G: LSTM cell, update h/c (4 rows x 2 cols) ----
#pragma unroll
            for (int i = 0; i < 4; i++) {
                float2 u0 = unpack2(acc[i][0]), u1 = unpack2(acc[i][1]);
                float2 u2 = unpack2(acc[i][2]), u3 = unpack2(acc[i][3]);
                float co0 = Acs[(64 + j0) * 64 + r0 + i];
                float co1 = Acs[(64 + j0 + 1) * 64 + r0 + i];
                float cn0 = sigf(u0.y) * co0 + sigf(u0.x) * tanh_acc(u1.x);
                float hn0 = sigf(u1.y) * tanh_acc(cn0);
                float cn1 = sigf(u2.y) * co1 + sigf(u2.x) * tanh_acc(u3.x);
                float hn1 = sigf(u3.y) * tanh_acc(cn1);
                Acs[(j0) * 64 + r0 + i]          = hn0;
                Acs[(j0 + 1) * 64 + r0 + i]      = hn1;
                Acs[(64 + j0) * 64 + r0 + i]     = cn0;
                Acs[(64 + j0 + 1) * 64 + r0 + i] = cn1;
            }
            __syncthreads();
        }

        // ---- out = [h | ctx] @ fcout_w^T + fcout_b ----
        if (tid < 5 * 64) {
            int row = tid & 63, o = tid >> 6;
            float s = fob_s[o];
            const float* fw = fow_s + o * 128;
#pragma unroll 8
            for (int k = 0; k < 64; k++) s = fmaf(fw[k], Acs[k * 64 + row], s);
            const float* cx = ctx_s + row * CSTR;
#pragma unroll 8
            for (int k = 0; k < 64; k++) s = fmaf(fw[64 + k], cx[k], s);
            out[(size_t)(b0 + row) * OUT + o] = s;
        }
    }
}

// =============================================================
// launcher
// =============================================================
extern "C" void kernel_launch(void* const* d_in, const int* in_sizes, int n_in,
                              void* d_out, int out_size) {
    const float* x           = (const float*)d_in[0];
    const float* y_hist      = (const float*)d_in[1];
    const float* h0_enc      = (const float*)d_in[2];
    const float* c0_enc      = (const float*)d_in[3];
    const float* h0_dec      = (const float*)d_in[4];
    const float* c0_dec      = (const float*)d_in[5];
    const float* enc_attn_w  = (const float*)d_in[6];
    // d_in[7] enc_attn_b: softmax-shift-invariant, unused
    const float* enc_Wih     = (const float*)d_in[8];
    const float* enc_Whh     = (const float*)d_in[9];
    const float* enc_bih     = (const float*)d_in[10];
    const float* enc_bhh     = (const float*)d_in[11];
    const float* dec_attn_w1 = (const float*)d_in[12];
    const float* dec_attn_b1 = (const float*)d_in[13];
    const float* dec_attn_w2 = (const float*)d_in[14];
    // d_in[15] dec_attn_b2: softmax-shift-invariant, unused
    const float* dec_Wih     = (const float*)d_in[16];
    const float* dec_Whh     = (const float*)d_in[17];
    const float* dec_bih     = (const float*)d_in[18];
    const float* dec_bhh     = (const float*)d_in[19];
    const float* fc_w        = (const float*)d_in[20];
    const float* fc_b        = (const float*)d_in[21];
    const float* fcout_w     = (const float*)d_in[22];
    const float* fcout_b     = (const float*)d_in[23];
    float* out = (float*)d_out;

    const int enc_sm = (192 * 64 + 2 * 32 * G4 + 64 * 64) * 4;          // 131072 B
    const int dec_sm = (69 * G4 + 128 * H + 128 * 64 + 5 * 64 +
                        64 * QSTR + 64 * CSTR + 64 + 64 +
                        5 * 72 + 8 + 5 * 128 + 8) * 4;                  // ~176.9 KB
    const int net_smem = (enc_sm > dec_sm) ? enc_sm : dec_sm;
    cudaFuncSetAttribute(k_net, cudaFuncAttributeMaxDynamicSharedMemorySize, net_smem);

    const int repack_n = 192 * G4 + 69 * G4 + 128 * H;
    k_repack<<<(repack_n + 255) / 256, 256>>>(
        enc_Wih, enc_Whh, dec_Wih, dec_Whh, dec_attn_w1);
    k_net<<<B / TILE, NTHR, net_smem>>>(
        x, h0_enc, c0_enc, enc_bih, enc_bhh, enc_attn_w, dec_attn_w1,
        y_hist, h0_dec, c0_dec, dec_attn_b1, dec_attn_w2,
        dec_bih, dec_bhh, fc_w, fc_b, fcout_w, fcout_b, out);
}